// round 2
// baseline (speedup 1.0000x reference)
#include <cuda_runtime.h>

// out[p, i*16+j] = x[p, i] * W[i, j] + b[i, j]
//   p in [0, B*T), i in [0,128), j in [0,16)
// x: [P, 128] f32, W: [128,16] f32, b: [128,16] f32, out: [P, 2048] f32
//
// Thread i (0..127) owns feature row i: W/b row held in registers.
// Loop over positions; coalesced x reads, contiguous 128-bit stores.

#define C_IN   128
#define C_OUT  16
#define POS_PER_BLOCK 8

__global__ __launch_bounds__(C_IN) void realembed_kernel(
    const float* __restrict__ x,
    const float* __restrict__ W,
    const float* __restrict__ bias,
    float* __restrict__ out,
    int P)
{
    const int i = threadIdx.x;              // feature index 0..127

    // Preload this feature's 16 weights + 16 biases into registers.
    const float4* Wr = reinterpret_cast<const float4*>(W    + i * C_OUT);
    const float4* Br = reinterpret_cast<const float4*>(bias + i * C_OUT);
    const float4 w0 = Wr[0], w1 = Wr[1], w2 = Wr[2], w3 = Wr[3];
    const float4 b0 = Br[0], b1 = Br[1], b2 = Br[2], b3 = Br[3];

    int p0 = blockIdx.x * POS_PER_BLOCK;
    int p1 = p0 + POS_PER_BLOCK;
    if (p1 > P) p1 = P;

    #pragma unroll 2
    for (int p = p0; p < p1; ++p) {
        const float xv = __ldg(x + (size_t)p * C_IN + i);

        float4 o0, o1, o2, o3;
        o0.x = fmaf(xv, w0.x, b0.x); o0.y = fmaf(xv, w0.y, b0.y);
        o0.z = fmaf(xv, w0.z, b0.z); o0.w = fmaf(xv, w0.w, b0.w);
        o1.x = fmaf(xv, w1.x, b1.x); o1.y = fmaf(xv, w1.y, b1.y);
        o1.z = fmaf(xv, w1.z, b1.z); o1.w = fmaf(xv, w1.w, b1.w);
        o2.x = fmaf(xv, w2.x, b2.x); o2.y = fmaf(xv, w2.y, b2.y);
        o2.z = fmaf(xv, w2.z, b2.z); o2.w = fmaf(xv, w2.w, b2.w);
        o3.x = fmaf(xv, w3.x, b3.x); o3.y = fmaf(xv, w3.y, b3.y);
        o3.z = fmaf(xv, w3.z, b3.z); o3.w = fmaf(xv, w3.w, b3.w);

        float4* dst = reinterpret_cast<float4*>(
            out + (size_t)p * (C_IN * C_OUT) + i * C_OUT);
        dst[0] = o0; dst[1] = o1; dst[2] = o2; dst[3] = o3;
    }
}

extern "C" void kernel_launch(void* const* d_in, const int* in_sizes, int n_in,
                              void* d_out, int out_size)
{
    const float* x  = (const float*)d_in[0];   // [B*T, 128]
    const float* W  = (const float*)d_in[1];   // [128, 16]
    const float* b  = (const float*)d_in[2];   // [128, 16]
    float* out = (float*)d_out;                // [B*T, 2048]

    const int P = in_sizes[0] / C_IN;          // B*T = 32768

    const int blocks = (P + POS_PER_BLOCK - 1) / POS_PER_BLOCK;
    realembed_kernel<<<blocks, C_IN>>>(x, W, b, out, P);
}

// round 5
// speedup vs baseline: 1.9275x; 1.9275x over previous
#include <cuda_runtime.h>

// out[p, i*16+j] = x[p, i] * W[i, j] + b[i, j]
//   p in [0, P=B*T), i in [0,128), j in [0,16)
// x: [P, 128] f32, W: [128,16] f32, b: [128,16] f32, out: [P, 2048] f32
//
// Chunk-per-thread mapping: 512 threads per block; thread t owns float4
// chunk t of every position it processes (feature i = t>>2, quad q = t&3).
// A warp's STG.128 covers 512 contiguous bytes (16 full 32B sectors).
// Streaming stores (__stcs): output is write-once, never re-read.

#define C_IN   128
#define C_OUT  16
#define CHUNKS 512            // 2048 floats / 4 per position
#define POS_PER_BLOCK 8
#define UNROLL 4

__global__ __launch_bounds__(CHUNKS) void realembed_kernel(
    const float* __restrict__ x,
    const float* __restrict__ W,
    const float* __restrict__ bias,
    float* __restrict__ out,
    int P)
{
    const int t = threadIdx.x;            // chunk index 0..511
    const int i = t >> 2;                 // feature 0..127
    const int q = t & 3;                  // quad within the 16 outputs

    // This thread's 4 weights + 4 biases.
    const float4 w4 = *reinterpret_cast<const float4*>(W    + i * C_OUT + q * 4);
    const float4 b4 = *reinterpret_cast<const float4*>(bias + i * C_OUT + q * 4);

    int p0 = blockIdx.x * POS_PER_BLOCK;
    int p1 = p0 + POS_PER_BLOCK;
    if (p1 > P) p1 = P;

    int p = p0;
    // Main unrolled body: 4 independent loads in flight, then 4 stores.
    for (; p + UNROLL <= p1; p += UNROLL) {
        float xv[UNROLL];
        #pragma unroll
        for (int k = 0; k < UNROLL; ++k)
            xv[k] = __ldg(x + (size_t)(p + k) * C_IN + i);

        #pragma unroll
        for (int k = 0; k < UNROLL; ++k) {
            float4 o;
            o.x = fmaf(xv[k], w4.x, b4.x);
            o.y = fmaf(xv[k], w4.y, b4.y);
            o.z = fmaf(xv[k], w4.z, b4.z);
            o.w = fmaf(xv[k], w4.w, b4.w);
            __stcs(reinterpret_cast<float4*>(out) + (size_t)(p + k) * CHUNKS + t, o);
        }
    }
    // Tail (P divisible by 8 in practice, but keep it correct).
    for (; p < p1; ++p) {
        float xv = __ldg(x + (size_t)p * C_IN + i);
        float4 o;
        o.x = fmaf(xv, w4.x, b4.x);
        o.y = fmaf(xv, w4.y, b4.y);
        o.z = fmaf(xv, w4.z, b4.z);
        o.w = fmaf(xv, w4.w, b4.w);
        __stcs(reinterpret_cast<float4*>(out) + (size_t)p * CHUNKS + t, o);
    }
}

extern "C" void kernel_launch(void* const* d_in, const int* in_sizes, int n_in,
                              void* d_out, int out_size)
{
    const float* x  = (const float*)d_in[0];   // [P, 128]
    const float* W  = (const float*)d_in[1];   // [128, 16]
    const float* b  = (const float*)d_in[2];   // [128, 16]
    float* out = (float*)d_out;                // [P, 2048]

    const int P = in_sizes[0] / C_IN;          // B*T = 32768

    const int blocks = (P + POS_PER_BLOCK - 1) / POS_PER_BLOCK;
    realembed_kernel<<<blocks, CHUNKS>>>(x, W, b, out, P);
}